// round 15
// baseline (speedup 1.0000x reference)
#include <cuda_runtime.h>
#include <cuda_fp16.h>
#include <cstdint>

#define BZ 4
#define DD 768
#define LL 4096
#define MM (BZ * LL)   // 16384
#define BKC 64
#define NKC 12         // 768 / 64 k-chunks
#define AS_STRIDE 72   // padded halfs per smem row (144B, ldmatrix conflict-free)
#define STAGE_BYTES (128 * AS_STRIDE * 2)  // 18432
#define NSTAGE 3
#define SM_TOTAL (NSTAGE * 2 * STAGE_BYTES)  // 110592

// Scratch (static device memory; no runtime alloc)
__device__ __align__(16) __half g_u[MM * DD];       // U (fp16)
__device__ __align__(16) __half g_q[MM * DD];       // Q (fp16)
__device__ __align__(16) __half g_xa[MM * DD];      // Xh input, later B2h
__device__ __align__(16) __half g_a[MM * DD];       // relu(U) half, later z half
__device__ __align__(16) __half g_wih[DD * DD];     // W_ih fp16
__device__ __align__(16) __half g_whh[DD * DD];     // W_hh fp16

// ---------------------------------------------------------------------------
// PTX helpers (plain sm_80-era ISA: valid on virtual compute_103)
// ---------------------------------------------------------------------------
__device__ __forceinline__ uint32_t smem_u32(const void* p) {
    uint32_t a;
    asm("{ .reg .u64 t; cvta.to.shared.u64 t, %1; cvt.u32.u64 %0, t; }" : "=r"(a) : "l"(p));
    return a;
}
__device__ __forceinline__ void cp_async16(uint32_t saddr, const void* gaddr) {
    asm volatile("cp.async.cg.shared.global [%0], [%1], 16;" :: "r"(saddr), "l"(gaddr));
}
__device__ __forceinline__ void cp_commit() {
    asm volatile("cp.async.commit_group;");
}
__device__ __forceinline__ void cp_wait1() {
    asm volatile("cp.async.wait_group 1;");
}
__device__ __forceinline__ void ldm_x4(uint32_t& r0, uint32_t& r1, uint32_t& r2, uint32_t& r3,
                                       uint32_t addr) {
    asm volatile("ldmatrix.sync.aligned.m8n8.x4.shared.b16 {%0,%1,%2,%3}, [%4];"
                 : "=r"(r0), "=r"(r1), "=r"(r2), "=r"(r3) : "r"(addr));
}
__device__ __forceinline__ void mma16816(float* c, const uint32_t* a, const uint32_t* b) {
    asm volatile(
        "mma.sync.aligned.m16n8k16.row.col.f32.f16.f16.f32 "
        "{%0,%1,%2,%3}, {%4,%5,%6,%7}, {%8,%9}, {%0,%1,%2,%3};"
        : "+f"(c[0]), "+f"(c[1]), "+f"(c[2]), "+f"(c[3])
        : "r"(a[0]), "r"(a[1]), "r"(a[2]), "r"(a[3]), "r"(b[0]), "r"(b[1]));
}

// ---------------------------------------------------------------------------
// HMMA GEMM: acc[M,768] = A[M,768] @ Wh[768,768]^T
// BM=BN=128, BK=64, 8 warps (4x2), warp tile 32x64, 3-stage cp.async.
// MODE 0: C = half(acc + bias1 + bias2); Aux = half(relu(same))    [GEMM1]
// MODE 1: shift-fuse: Aux[r+1] = relu(U[r+1] + acc[r]); t=0 rows
//         get relu(U[r]); C unused.                                 [GEMM2]
// MODE 2: C = half(acc)                                             [GEMM3]
// ---------------------------------------------------------------------------
template <int MODE>
__global__ __launch_bounds__(256, 2) void gemm_hmma(
    const __half* __restrict__ A, const __half* __restrict__ Bh,
    const float* __restrict__ bias1, const float* __restrict__ bias2,
    const __half* __restrict__ U,       // MODE 1 only
    __half* __restrict__ C, __half* __restrict__ Aux) {
    extern __shared__ __align__(16) unsigned char smem[];
    const uint32_t sa_base = smem_u32(smem);                       // A stages
    const uint32_t sb_base = sa_base + NSTAGE * STAGE_BYTES;       // B stages

    const int tid = threadIdx.x;
    const int wid = tid >> 5, lane = tid & 31;
    const int m0 = blockIdx.y * 128, n0 = blockIdx.x * 128;
    const int warp_m = (wid >> 1) * 32;   // 0,32,64,96
    const int warp_n = (wid & 1) * 64;    // 0,64

    const int cr = tid >> 3;          // row base 0..31 (+q*32)
    const int cc = (tid & 7) * 8;     // half col 0..56

    float acc[2][8][4] = {};

    const int a_row = warp_m + (lane & 7) + ((lane >> 3) & 1) * 8;  // + mt*16
    const int a_colh = (lane >> 4) * 8;                              // + ks*16
    const int b_row = warp_n + (lane & 7) + (lane >> 4) * 8;         // + j*16
    const int b_colh = ((lane >> 3) & 1) * 8;                        // + ks*16

    auto load_stage = [&](int chunk, int stage) {
        const int kb = chunk * BKC;
        const uint32_t sa = sa_base + stage * STAGE_BYTES;
        const uint32_t sb = sb_base + stage * STAGE_BYTES;
        #pragma unroll
        for (int q = 0; q < 4; ++q) {
            const int r = cr + q * 32;
            cp_async16(sa + (r * AS_STRIDE + cc) * 2, A + (size_t)(m0 + r) * DD + kb + cc);
            cp_async16(sb + (r * AS_STRIDE + cc) * 2, Bh + (size_t)(n0 + r) * DD + kb + cc);
        }
    };

    load_stage(0, 0); cp_commit();
    load_stage(1, 1); cp_commit();

    for (int i = 0; i < NKC; ++i) {
        cp_wait1();
        __syncthreads();
        if (i + 2 < NKC) load_stage(i + 2, (i + 2) % NSTAGE);
        cp_commit();

        const int st = i % NSTAGE;
        const uint32_t a_st = sa_base + st * STAGE_BYTES;
        const uint32_t b_st = sb_base + st * STAGE_BYTES;

        #pragma unroll
        for (int ks = 0; ks < 4; ++ks) {
            uint32_t af[2][4], bf[8][2];
            #pragma unroll
            for (int mt = 0; mt < 2; ++mt)
                ldm_x4(af[mt][0], af[mt][1], af[mt][2], af[mt][3],
                       a_st + ((a_row + mt * 16) * AS_STRIDE + a_colh + ks * 16) * 2);
            #pragma unroll
            for (int j = 0; j < 4; ++j)
                ldm_x4(bf[2 * j][0], bf[2 * j][1], bf[2 * j + 1][0], bf[2 * j + 1][1],
                       b_st + ((b_row + j * 16) * AS_STRIDE + b_colh + ks * 16) * 2);
            #pragma unroll
            for (int mt = 0; mt < 2; ++mt)
                #pragma unroll
                for (int nt = 0; nt < 8; ++nt)
                    mma16816(acc[mt][nt], af[mt], bf[nt]);
        }
    }

    // epilogue
    #pragma unroll
    for (int mt = 0; mt < 2; ++mt) {
        #pragma unroll
        for (int h = 0; h < 2; ++h) {
            const int row = m0 + warp_m + mt * 16 + (lane >> 2) + h * 8;
            const int colb = n0 + warp_n + (lane & 3) * 2;
            #pragma unroll
            for (int nt = 0; nt < 8; ++nt) {
                float vx = acc[mt][nt][h * 2 + 0];
                float vy = acc[mt][nt][h * 2 + 1];
                const size_t off = (size_t)row * DD + colb + nt * 8;
                if (MODE == 0) {
                    const int n = colb + nt * 8;
                    vx += bias1[n + 0] + bias2[n + 0];
                    vy += bias1[n + 1] + bias2[n + 1];
                    __half hh[2];
                    hh[0] = __float2half_rn(vx);
                    hh[1] = __float2half_rn(vy);
                    *(uint32_t*)(C + off) = *(const uint32_t*)hh;
                    __half rr[2];
                    rr[0] = __float2half_rn(fmaxf(vx, 0.f));
                    rr[1] = __float2half_rn(fmaxf(vy, 0.f));
                    *(uint32_t*)(Aux + off) = *(const uint32_t*)rr;
                } else if (MODE == 1) {
                    // B2[row+1] = relu(U[row+1] + P[row]) unless row+1 is a batch start
                    if (((row + 1) & (LL - 1)) != 0) {
                        uint32_t upack = *(const uint32_t*)(U + off + DD);
                        __half2 u2 = *(__half2*)&upack;
                        __half rr[2];
                        rr[0] = __float2half_rn(fmaxf(__low2float(u2) + vx, 0.f));
                        rr[1] = __float2half_rn(fmaxf(__high2float(u2) + vy, 0.f));
                        *(uint32_t*)(Aux + off + DD) = *(const uint32_t*)rr;
                    }
                    // batch-start rows: B2[row] = relu(U[row])
                    if ((row & (LL - 1)) == 0) {
                        uint32_t upack = *(const uint32_t*)(U + off);
                        __half2 u2 = *(__half2*)&upack;
                        __half rr[2];
                        rr[0] = __float2half_rn(fmaxf(__low2float(u2), 0.f));
                        rr[1] = __float2half_rn(fmaxf(__high2float(u2), 0.f));
                        *(uint32_t*)(Aux + off) = *(const uint32_t*)rr;
                    }
                } else {
                    __half hh[2];
                    hh[0] = __float2half_rn(vx);
                    hh[1] = __float2half_rn(vy);
                    *(uint32_t*)(C + off) = *(const uint32_t*)hh;
                }
            }
        }
    }
}

// ---------------------------------------------------------------------------
// Elementwise / prep kernels
// ---------------------------------------------------------------------------
// W [768,768] fp32 -> half
__global__ void conv_w_kernel(const float* __restrict__ W, __half* __restrict__ Wh) {
    int idx = blockIdx.x * 256 + threadIdx.x;
    if (idx >= DD * DD) return;
    Wh[idx] = __float2half_rn(W[idx]);
}

// x [B,D,L] fp32 -> Xh [B*L, 768] half (transpose + cast)
__global__ void conv_x_kernel(const float* __restrict__ x, __half* __restrict__ Xh) {
    __shared__ float tile[32][33];
    int b = blockIdx.z, t0 = blockIdx.x * 32, d0 = blockIdx.y * 32;
    int tx = threadIdx.x;
    #pragma unroll
    for (int i = threadIdx.y; i < 32; i += 8)
        tile[tx][i] = x[(size_t)(b * DD + d0 + i) * LL + t0 + tx];
    __syncthreads();
    #pragma unroll
    for (int i = threadIdx.y; i < 32; i += 8)
        Xh[(size_t)(b * LL + t0 + i) * DD + d0 + tx] = __float2half_rn(tile[i][tx]);
}

// z = transpose(relu(U + shift(Q))) + x -> [B, D, L] fp16
__global__ void c3_transpose_kernel(const __half* __restrict__ U, const __half* __restrict__ Q,
                                    const float* __restrict__ x, __half* __restrict__ z) {
    __shared__ float tile[32][33];
    int b = blockIdx.z, t0 = blockIdx.x * 32, d0 = blockIdx.y * 32;
    int tx = threadIdx.x;
    #pragma unroll
    for (int i = threadIdx.y; i < 32; i += 8) {
        int t = t0 + i;
        int r = b * LL + t;
        float u = __half2float(U[(size_t)r * DD + d0 + tx]);
        float q = (t > 0) ? __half2float(Q[(size_t)(r - 1) * DD + d0 + tx]) : 0.f;
        tile[i][tx] = fmaxf(u + q, 0.f);
    }
    __syncthreads();
    #pragma unroll
    for (int i = threadIdx.y; i < 32; i += 8) {
        size_t o = (size_t)(b * DD + d0 + i) * LL + t0 + tx;
        z[o] = __float2half_rn(tile[tx][i] + x[o]);
    }
}

// LayerNorm over L per (b,d) row; input z fp16, output fp32
__global__ __launch_bounds__(256) void layernorm_kernel(
    const __half* __restrict__ z,
    const float* __restrict__ gamma, const float* __restrict__ beta,
    float* __restrict__ out) {
    __shared__ __align__(16) float zbuf[LL];
    __shared__ float red[256];
    int row = blockIdx.x;
    int tid = threadIdx.x;
    const uint4* z8 = (const uint4*)(z + (size_t)row * LL);
    float4* o4 = (float4*)(out + (size_t)row * LL);
    const float4* g4 = (const float4*)gamma;
    const float4* be4 = (const float4*)beta;

    float s = 0.f;
    #pragma unroll
    for (int i = tid; i < LL / 8; i += 256) {
        uint4 pk = z8[i];
        __half2* h2 = (__half2*)&pk;
        #pragma unroll
        for (int j = 0; j < 4; ++j) {
            float2 f = __half22float2(h2[j]);
            zbuf[i * 8 + j * 2 + 0] = f.x;
            zbuf[i * 8 + j * 2 + 1] = f.y;
            s += f.x + f.y;
        }
    }
    red[tid] = s;
    __syncthreads();
    #pragma unroll
    for (int o = 128; o > 0; o >>= 1) {
        if (tid < o) red[tid] += red[tid + o];
        __syncthreads();
    }
    float mean = red[0] * (1.f / LL);
    __syncthreads();

    float v = 0.f;
    #pragma unroll
    for (int i = tid; i < LL / 4; i += 256) {
        float4 zz = ((float4*)zbuf)[i];
        float dx = zz.x - mean, dy = zz.y - mean, dz = zz.z - mean, dw = zz.w - mean;
        v += dx * dx + dy * dy + dz * dz + dw * dw;
    }
    red[tid] = v;
    __syncthreads();
    #pragma unroll
    for (int o = 128; o > 0; o >>= 1) {
        if (tid < o) red[tid] += red[tid + o];
        __syncthreads();
    }
    float rstd = rsqrtf(red[0] * (1.f / LL) + 1e-12f);

    #pragma unroll
    for (int i = tid; i < LL / 4; i += 256) {
        float4 zz = ((float4*)zbuf)[i];
        float4 g = g4[i], bb = be4[i];
        float4 o;
        o.x = (zz.x - mean) * rstd * g.x + bb.x;
        o.y = (zz.y - mean) * rstd * g.y + bb.y;
        o.z = (zz.z - mean) * rstd * g.z + bb.z;
        o.w = (zz.w - mean) * rstd * g.w + bb.w;
        o4[i] = o;
    }
}

// ---------------------------------------------------------------------------
// Launch
// ---------------------------------------------------------------------------
extern "C" void kernel_launch(void* const* d_in, const int* in_sizes, int n_in,
                              void* d_out, int out_size) {
    const float* x = (const float*)d_in[0];
    const float* W_ih = (const float*)d_in[1];
    const float* W_hh = (const float*)d_in[2];
    const float* b_ih = (const float*)d_in[3];
    const float* b_hh = (const float*)d_in[4];
    const float* gamma = (const float*)d_in[5];
    const float* beta = (const float*)d_in[6];
    float* out = (float*)d_out;

    __half *pu, *pq, *pxa, *pa, *pwih, *pwhh;
    cudaGetSymbolAddress((void**)&pu, g_u);
    cudaGetSymbolAddress((void**)&pq, g_q);
    cudaGetSymbolAddress((void**)&pxa, g_xa);
    cudaGetSymbolAddress((void**)&pa, g_a);
    cudaGetSymbolAddress((void**)&pwih, g_wih);
    cudaGetSymbolAddress((void**)&pwhh, g_whh);

    cudaFuncSetAttribute(gemm_hmma<0>, cudaFuncAttributeMaxDynamicSharedMemorySize, SM_TOTAL);
    cudaFuncSetAttribute(gemm_hmma<1>, cudaFuncAttributeMaxDynamicSharedMemorySize, SM_TOTAL);
    cudaFuncSetAttribute(gemm_hmma<2>, cudaFuncAttributeMaxDynamicSharedMemorySize, SM_TOTAL);

    dim3 tgrid(LL / 32, DD / 32, BZ), tblk(32, 8);
    dim3 ggrid(DD / 128, MM / 128);  // (6, 128)

    // W casts
    conv_w_kernel<<<(DD * DD + 255) / 256, 256>>>(W_ih, pwih);
    conv_w_kernel<<<(DD * DD + 255) / 256, 256>>>(W_hh, pwhh);
    // Xh = half(transpose(x))
    conv_x_kernel<<<tgrid, tblk>>>(x, pxa);
    // U = X @ W_ih^T + b_ih + b_hh (half -> g_u); relu(U) -> g_a
    gemm_hmma<0><<<ggrid, 256, SM_TOTAL>>>(pxa, pwih, b_ih, b_hh, nullptr, pu, pa);
    // P = relu(U) @ W_hh^T; fused: B2 = relu(U + shift(P)) -> g_xa
    gemm_hmma<1><<<ggrid, 256, SM_TOTAL>>>(pa, pwhh, nullptr, nullptr, pu, nullptr, pxa);
    // Q = B2 @ W_hh^T -> g_q
    gemm_hmma<2><<<ggrid, 256, SM_TOTAL>>>(pxa, pwhh, nullptr, nullptr, nullptr, pq, nullptr);
    // z = transpose(relu(U + shift(Q))) + x -> g_a (fp16, [B,D,L])
    c3_transpose_kernel<<<tgrid, tblk>>>(pu, pq, x, pa);
    // out = LayerNorm_L(z)
    layernorm_kernel<<<BZ * DD, 256>>>(pa, gamma, beta, out);
}